// round 1
// baseline (speedup 1.0000x reference)
#include <cuda_runtime.h>
#include <cuda_bf16.h>
#include <math.h>

#define B_ 2
#define S_ 2048
#define D_ 1024
#define H_ 16
#define HD 64
#define BH_ (B_*H_)
#define KAD 128
#define MROWS (B_*S_)

// scratch (static device arrays; no allocation allowed)
__device__ float g_q[MROWS * D_];
__device__ float g_k[MROWS * D_];
__device__ float g_v[MROWS * D_];
__device__ float g_qa[BH_ * KAD * S_];   // [bh][kk][s] k-major
__device__ float g_ka[BH_ * KAD * S_];
__device__ float g_o[BH_ * S_ * HD];
__device__ float g_m[MROWS * D_];

// ---------------------------------------------------------------------------
// GEMM: C[m,n] = sum_k A[m,k] * W[n,k].  M mult of 128, N=1024, K=1024.
// 128x128 tile, BK=8, 256 threads, 8x8 micro-tile (split 4+4 layout).
// ---------------------------------------------------------------------------
__global__ __launch_bounds__(256) void gemm_nt(const float* __restrict__ A,
                                               const float* __restrict__ W,
                                               float* __restrict__ C) {
  const int K = 1024, N = 1024;
  __shared__ float As[8][128];
  __shared__ float Bs[8][128];
  int tid = threadIdx.x;
  int m0 = blockIdx.x * 128;
  int n0 = blockIdx.y * 128;
  int tx = tid & 15, ty = tid >> 4;
  int lrow = tid >> 1;
  int lk = (tid & 1) * 4;
  const float* Ap = A + (size_t)(m0 + lrow) * K + lk;
  const float* Wp = W + (size_t)(n0 + lrow) * K + lk;
  float c[8][8] = {};
  for (int kt = 0; kt < K; kt += 8) {
    float4 av = *(const float4*)(Ap + kt);
    float4 wv = *(const float4*)(Wp + kt);
    As[lk+0][lrow]=av.x; As[lk+1][lrow]=av.y; As[lk+2][lrow]=av.z; As[lk+3][lrow]=av.w;
    Bs[lk+0][lrow]=wv.x; Bs[lk+1][lrow]=wv.y; Bs[lk+2][lrow]=wv.z; Bs[lk+3][lrow]=wv.w;
    __syncthreads();
#pragma unroll
    for (int k = 0; k < 8; k++) {
      float4 a0 = *(const float4*)&As[k][ty*4];
      float4 a1 = *(const float4*)&As[k][64 + ty*4];
      float4 b0 = *(const float4*)&Bs[k][tx*4];
      float4 b1 = *(const float4*)&Bs[k][64 + tx*4];
      float ar[8] = {a0.x,a0.y,a0.z,a0.w,a1.x,a1.y,a1.z,a1.w};
      float br[8] = {b0.x,b0.y,b0.z,b0.w,b1.x,b1.y,b1.z,b1.w};
#pragma unroll
      for (int i=0;i<8;i++)
#pragma unroll
        for (int j=0;j<8;j++)
          c[i][j] = fmaf(ar[i], br[j], c[i][j]);
    }
    __syncthreads();
  }
#pragma unroll
  for (int i=0;i<8;i++) {
    int m = m0 + (i<4 ? ty*4+i : 64 + ty*4 + (i-4));
    float4 v0 = make_float4(c[i][0],c[i][1],c[i][2],c[i][3]);
    float4 v1 = make_float4(c[i][4],c[i][5],c[i][6],c[i][7]);
    *(float4*)(C + (size_t)m*N + n0 + tx*4) = v0;
    *(float4*)(C + (size_t)m*N + n0 + 64 + tx*4) = v1;
  }
}

// ---------------------------------------------------------------------------
// RoPE + augmentation + transpose.
// src: [b*S+s][D] (head h block of 64).  dst: [bh][kk=0..127][s], where
// kk<64 = roped value, kk>=64 = sq_scale * roped^2.
// ---------------------------------------------------------------------------
__global__ __launch_bounds__(256) void rope_augment(const float* __restrict__ src,
                                                    float* __restrict__ dst,
                                                    float sq_scale) {
  int bh = blockIdx.y;
  int b = bh >> 4, h = bh & 15;
  int s0 = blockIdx.x * 64;
  __shared__ float ts[64][65];
  int tid = threadIdx.x;
  const float* base = src + ((size_t)(b*S_ + s0))*D_ + h*HD;
#pragma unroll
  for (int r = 0; r < 4; r++) {
    int e = (tid + r*256) * 4;
    int srow = e >> 6;
    int d0 = e & 63;
    float4 v = *(const float4*)(base + (size_t)srow*D_ + d0);
    ts[srow][d0+0]=v.x; ts[srow][d0+1]=v.y; ts[srow][d0+2]=v.z; ts[srow][d0+3]=v.w;
  }
  __syncthreads();
  int s_off = tid & 63;
  int kb = tid >> 6;
  int s_glob = s0 + s_off;
  float* dbase = dst + (size_t)bh * KAD * S_;
  for (int kk = kb; kk < KAD; kk += 4) {
    int d = kk & 63;
    int p = d & 31;
    float invf = (float)(1.0 / pow(10000.0, (double)p / 32.0));
    float ang = (float)s_glob * invf;
    float cs, sn;
    sincosf(ang, &sn, &cs);
    float t1 = ts[s_off][p], t2 = ts[s_off][p+32];
    float r = (d < 32) ? (t1*cs - t2*sn) : (t2*cs + t1*sn);
    float val = (kk < 64) ? r : sq_scale * r * r;
    dbase[(size_t)kk * S_ + s_glob] = val;
  }
}

// ---------------------------------------------------------------------------
// Flash attention (causal), augmented head dim 128, fp32 online softmax.
// Grid: (32 q-blocks reversed, 32 bh).  64q x 64k tiles, 256 thr, 4x4 micro.
// QA/KA k-major [bh][128][S]; V natural [b*S+s][D]; O [bh][s][64].
// ---------------------------------------------------------------------------
__global__ __launch_bounds__(256) void flash_kernel(const float* __restrict__ QA,
                                                    const float* __restrict__ KA,
                                                    const float* __restrict__ V,
                                                    float* __restrict__ O) {
  int bh = blockIdx.y;
  int qi = (int)gridDim.x - 1 - (int)blockIdx.x;   // heavy blocks launch first
  int b = bh >> 4, h = bh & 15;
  extern __shared__ float sm[];
  float* Qs = sm;           // [128][64] k-major
  float* Ks = sm + 8192;    // [128][64] k-major
  float* Vs = sm + 16384;   // [64][64]  t-major (natural)
  float* Ps = sm + 20480;   // [64][64]  t-major, xor-swizzled chunks
  int tid = threadIdx.x;
  int tx = tid & 15, ty = tid >> 4;

  const float* qb = QA + (size_t)bh * KAD * S_ + qi * 64;
#pragma unroll
  for (int r = 0; r < 8; r++) {
    int e = (tid + r*256) * 4;
    int kk = e >> 6, s4 = e & 63;
    *(float4*)&Qs[kk*64 + s4] = *(const float4*)(qb + (size_t)kk*S_ + s4);
  }
  float mrow[4], lrow[4], o[4][4];
#pragma unroll
  for (int i=0;i<4;i++){ mrow[i] = -1e30f; lrow[i]=0.f;
#pragma unroll
    for (int j=0;j<4;j++) o[i][j]=0.f; }
  const float* kbB = KA + (size_t)bh * KAD * S_;
  const float* vbB = V + (size_t)b * S_ * D_ + h * HD;
  __syncthreads();

  for (int kb = 0; kb <= qi; kb++) {
#pragma unroll
    for (int r = 0; r < 8; r++) {
      int e = (tid + r*256) * 4;
      int kk = e >> 6, s4 = e & 63;
      *(float4*)&Ks[kk*64 + s4] = *(const float4*)(kbB + (size_t)kk*S_ + kb*64 + s4);
    }
#pragma unroll
    for (int r = 0; r < 4; r++) {
      int e = (tid + r*256) * 4;
      int t = e >> 6, d4 = e & 63;
      *(float4*)&Vs[t*64 + d4] = *(const float4*)(vbB + (size_t)(kb*64 + t)*D_ + d4);
    }
    __syncthreads();

    float s[4][4] = {};
#pragma unroll 4
    for (int k = 0; k < 128; k++) {
      float4 a  = *(const float4*)&Qs[k*64 + ty*4];
      float4 bq = *(const float4*)&Ks[k*64 + tx*4];
      float ar[4]={a.x,a.y,a.z,a.w}, br[4]={bq.x,bq.y,bq.z,bq.w};
#pragma unroll
      for (int i=0;i<4;i++)
#pragma unroll
        for (int j=0;j<4;j++) s[i][j] = fmaf(ar[i], br[j], s[i][j]);
    }
    bool diag = (kb == qi);
#pragma unroll
    for (int i=0;i<4;i++)
#pragma unroll
      for (int j=0;j<4;j++) {
        float v = s[i][j] * 0.125f;   // 1/sqrt(64)
        if (diag && (tx*4+j) > (ty*4+i)) v = -1e30f;
        s[i][j] = v;
      }
    // online softmax (row stats reduced across the 16 tx lanes)
#pragma unroll
    for (int i=0;i<4;i++) {
      float mt = fmaxf(fmaxf(s[i][0],s[i][1]), fmaxf(s[i][2],s[i][3]));
#pragma unroll
      for (int off=8; off>0; off>>=1)
        mt = fmaxf(mt, __shfl_xor_sync(0xffffffffu, mt, off, 16));
      float mn = fmaxf(mrow[i], mt);
      float f  = __expf(mrow[i] - mn);
      float p0 = __expf(s[i][0]-mn), p1 = __expf(s[i][1]-mn);
      float p2 = __expf(s[i][2]-mn), p3 = __expf(s[i][3]-mn);
      float rs = p0+p1+p2+p3;
#pragma unroll
      for (int off=8; off>0; off>>=1)
        rs += __shfl_xor_sync(0xffffffffu, rs, off, 16);
      lrow[i] = lrow[i]*f + rs;
      mrow[i] = mn;
#pragma unroll
      for (int j=0;j<4;j++) o[i][j] *= f;
      s[i][0]=p0; s[i][1]=p1; s[i][2]=p2; s[i][3]=p3;
    }
    // store P t-major with xor chunk swizzle (conflict-light stores, clean reads)
#pragma unroll
    for (int j=0;j<4;j++) {
      int t = tx*4+j;
      int chunk = ty ^ (t & 15);
#pragma unroll
      for (int i=0;i<4;i++)
        Ps[t*64 + chunk*4 + i] = s[i][j];
    }
    __syncthreads();
    // O += P @ V
#pragma unroll 4
    for (int t=0;t<64;t++) {
      int chunk = ty ^ (t & 15);
      float4 a  = *(const float4*)&Ps[t*64 + chunk*4];
      float4 bv = *(const float4*)&Vs[t*64 + tx*4];
      float ar[4]={a.x,a.y,a.z,a.w}, br[4]={bv.x,bv.y,bv.z,bv.w};
#pragma unroll
      for (int i=0;i<4;i++)
#pragma unroll
        for (int j=0;j<4;j++) o[i][j] = fmaf(ar[i], br[j], o[i][j]);
    }
    __syncthreads();
  }

  float* ob = O + ((size_t)bh * S_ + (size_t)qi*64) * HD;
#pragma unroll
  for (int i=0;i<4;i++) {
    float inv = 1.0f / lrow[i];
    float4 v = make_float4(o[i][0]*inv, o[i][1]*inv, o[i][2]*inv, o[i][3]*inv);
    *(float4*)(ob + (size_t)(ty*4+i)*HD + tx*4) = v;
  }
}

// ---------------------------------------------------------------------------
// merge: out2==out1 algebraically, so out = o + 0.05*o^2*gate_w[d],
// plus layout transpose [bh][s][hd] -> [b*S+s][D]
// ---------------------------------------------------------------------------
__global__ __launch_bounds__(256) void merge_kernel(const float* __restrict__ O,
                                                    const float* __restrict__ gate,
                                                    float* __restrict__ Mo) {
  int idx = blockIdx.x * 256 + threadIdx.x;
  int d = idx & 63;
  int h = (idx >> 6) & 15;
  int row = idx >> 10;           // b*S+s
  int b = row >> 11;
  int s = row & 2047;
  float o = O[(((size_t)(b*16+h)*S_ + s) << 6) + d];
  float g = gate[d];
  Mo[idx] = o + 0.05f * o * o * g;
}

extern "C" void kernel_launch(void* const* d_in, const int* in_sizes, int n_in,
                              void* d_out, int out_size) {
  const float* x  = (const float*)d_in[0];
  const float* Wq = (const float*)d_in[1];
  const float* Wk = (const float*)d_in[2];
  const float* Wv = (const float*)d_in[3];
  const float* Wo = (const float*)d_in[4];
  const float* gw = (const float*)d_in[5];
  float* out = (float*)d_out;

  float *q, *k, *v, *qa, *ka, *o, *mrg;
  cudaGetSymbolAddress((void**)&q,  g_q);
  cudaGetSymbolAddress((void**)&k,  g_k);
  cudaGetSymbolAddress((void**)&v,  g_v);
  cudaGetSymbolAddress((void**)&qa, g_qa);
  cudaGetSymbolAddress((void**)&ka, g_ka);
  cudaGetSymbolAddress((void**)&o,  g_o);
  cudaGetSymbolAddress((void**)&mrg, g_m);

  dim3 gg(32, 8);
  gemm_nt<<<gg, 256>>>(x, Wq, q);
  gemm_nt<<<gg, 256>>>(x, Wk, k);
  gemm_nt<<<gg, 256>>>(x, Wv, v);

  dim3 gr(32, 32);
  rope_augment<<<gr, 256>>>(q, qa, 1.0f);
  rope_augment<<<gr, 256>>>(k, ka, 0.1f);   // lambda folded into K side (exact)

  cudaFuncSetAttribute(flash_kernel, cudaFuncAttributeMaxDynamicSharedMemorySize, 98304);
  flash_kernel<<<dim3(32, 32), 256, 98304>>>(qa, ka, v, o);

  merge_kernel<<<16384, 256>>>(o, gw, mrg);

  gemm_nt<<<gg, 256>>>(mrg, Wo, out);
}

// round 3
// speedup vs baseline: 3.0698x; 3.0698x over previous
#include <cuda_runtime.h>
#include <cuda_bf16.h>
#include <cstdint>
#include <stdint.h>
#include <math.h>

#define B_ 2
#define S_ 2048
#define D_ 1024
#define H_ 16
#define HD 64
#define BH_ (B_*H_)
#define KAD 128
#define MROWS (B_*S_)

typedef __nv_bfloat16 bf16;

// ---- scratch (static device arrays; no allocation allowed) ----
__device__ float g_q[MROWS * D_];
__device__ float g_k[MROWS * D_];
__device__ float g_v[MROWS * D_];
__device__ float g_o[BH_ * S_ * HD];
__device__ bf16 g_xh[MROWS * D_], g_xl[MROWS * D_];
__device__ bf16 g_wqh[D_*D_], g_wql[D_*D_];
__device__ bf16 g_wkh[D_*D_], g_wkl[D_*D_];
__device__ bf16 g_wvh[D_*D_], g_wvl[D_*D_];
__device__ bf16 g_woh[D_*D_], g_wol[D_*D_];
__device__ bf16 g_qah[BH_*S_*KAD], g_qal[BH_*S_*KAD];
__device__ bf16 g_kah[BH_*S_*KAD], g_kal[BH_*S_*KAD];
__device__ bf16 g_vh[MROWS * D_], g_vl[MROWS * D_];
__device__ bf16 g_mh[MROWS * D_], g_ml[MROWS * D_];

// ---- mma / ldmatrix helpers ----
__device__ __forceinline__ void ldsm4(uint32_t addr, uint32_t r[4]) {
  asm volatile("ldmatrix.sync.aligned.m8n8.x4.shared.b16 {%0,%1,%2,%3},[%4];"
    : "=r"(r[0]),"=r"(r[1]),"=r"(r[2]),"=r"(r[3]) : "r"(addr));
}
__device__ __forceinline__ void ldsm4t(uint32_t addr, uint32_t r[4]) {
  asm volatile("ldmatrix.sync.aligned.m8n8.x4.trans.shared.b16 {%0,%1,%2,%3},[%4];"
    : "=r"(r[0]),"=r"(r[1]),"=r"(r[2]),"=r"(r[3]) : "r"(addr));
}
__device__ __forceinline__ void mma_bf16(float c[4], const uint32_t a[4], const uint32_t b[2]) {
  asm volatile("mma.sync.aligned.m16n8k16.row.col.f32.bf16.bf16.f32 "
    "{%0,%1,%2,%3},{%4,%5,%6,%7},{%8,%9},{%0,%1,%2,%3};"
    : "+f"(c[0]),"+f"(c[1]),"+f"(c[2]),"+f"(c[3])
    : "r"(a[0]),"r"(a[1]),"r"(a[2]),"r"(a[3]),"r"(b[0]),"r"(b[1]));
}
__device__ __forceinline__ uint32_t packbf(float lo, float hi) {
  uint32_t r;
  asm("cvt.rn.bf16x2.f32 %0, %1, %2;" : "=r"(r) : "f"(hi), "f"(lo));
  return r;
}
// element offset for [rows][16] bf16 tiles, 2 chunks of 8 per row, conflict-free swizzle
__device__ __forceinline__ uint32_t swz16(int row, int h) {
  return (uint32_t)(row*16 + ((h ^ ((row>>2)&1)) << 3));
}

// ---------------------------------------------------------------------------
// split: fp32 -> bf16 hi + bf16 lo residual
// ---------------------------------------------------------------------------
__global__ __launch_bounds__(256) void split4(const float* __restrict__ in,
                                              bf16* __restrict__ h, bf16* __restrict__ l, int n4) {
  int i = blockIdx.x*256 + threadIdx.x;
  if (i >= n4) return;
  float4 v = ((const float4*)in)[i];
  bf16 hx = __float2bfloat16_rn(v.x), hy = __float2bfloat16_rn(v.y);
  bf16 hz = __float2bfloat16_rn(v.z), hw = __float2bfloat16_rn(v.w);
  __nv_bfloat162* hp = (__nv_bfloat162*)h;
  __nv_bfloat162* lp = (__nv_bfloat162*)l;
  hp[2*i]   = __nv_bfloat162(hx, hy);
  hp[2*i+1] = __nv_bfloat162(hz, hw);
  lp[2*i]   = __nv_bfloat162(__float2bfloat16_rn(v.x - __bfloat162float(hx)),
                             __float2bfloat16_rn(v.y - __bfloat162float(hy)));
  lp[2*i+1] = __nv_bfloat162(__float2bfloat16_rn(v.z - __bfloat162float(hz)),
                             __float2bfloat16_rn(v.w - __bfloat162float(hw)));
}

// ---------------------------------------------------------------------------
// GEMM (3-pass bf16 split): C[m,n] = sum_k A[m,k]*W[n,k], N=K=1024.
// 128x128 tile, bk=16, 256 threads / 8 warps, warp tile 32x64, double-buffered.
// ---------------------------------------------------------------------------
__global__ __launch_bounds__(256) void gemm_bf16(
    const bf16* __restrict__ Ah, const bf16* __restrict__ Al,
    const bf16* __restrict__ Bh, const bf16* __restrict__ Bl,
    float* __restrict__ C) {
  __shared__ __align__(16) bf16 sA[2][2][128*16];
  __shared__ __align__(16) bf16 sB[2][2][128*16];
  const int tid = threadIdx.x;
  const int w = tid >> 5, lane = tid & 31;
  const int wm = w & 3, wn = w >> 2;
  const int m0 = blockIdx.x * 128, n0 = blockIdx.y * 128;
  const int lrow = tid >> 1, lh = tid & 1;
  const uint4* pAh = (const uint4*)(Ah + (size_t)(m0+lrow)*D_);
  const uint4* pAl = (const uint4*)(Al + (size_t)(m0+lrow)*D_);
  const uint4* pBh = (const uint4*)(Bh + (size_t)(n0+lrow)*D_);
  const uint4* pBl = (const uint4*)(Bl + (size_t)(n0+lrow)*D_);
  const uint32_t soff = swz16(lrow, lh);

  uint4 va = pAh[lh], vb = pAl[lh], vc = pBh[lh], vd = pBl[lh];
  *(uint4*)&sA[0][0][soff] = va;  *(uint4*)&sA[0][1][soff] = vb;
  *(uint4*)&sB[0][0][soff] = vc;  *(uint4*)&sB[0][1][soff] = vd;
  __syncthreads();

  float acc[2][8][4];
#pragma unroll
  for (int m=0;m<2;m++)
#pragma unroll
    for (int n=0;n<8;n++)
#pragma unroll
      for (int e=0;e<4;e++) acc[m][n][e] = 0.f;

  const int ar = wm*32 + (lane & 15);
  const int ahalf = lane >> 4;
  const int brl = (lane & 7) + ((lane >> 4) << 3);
  const int bhalf = (lane >> 3) & 1;

  for (int kt = 0; kt < 64; kt++) {
    int cur = kt & 1;
    if (kt < 63) {
      va = pAh[(kt+1)*2 + lh]; vb = pAl[(kt+1)*2 + lh];
      vc = pBh[(kt+1)*2 + lh]; vd = pBl[(kt+1)*2 + lh];
    }
    uint32_t bAh = (uint32_t)__cvta_generic_to_shared(&sA[cur][0][0]);
    uint32_t bAl = (uint32_t)__cvta_generic_to_shared(&sA[cur][1][0]);
    uint32_t bBh = (uint32_t)__cvta_generic_to_shared(&sB[cur][0][0]);
    uint32_t bBl = (uint32_t)__cvta_generic_to_shared(&sB[cur][1][0]);

    uint32_t ah0[4], ah1[4], al0[4], al1[4];
    ldsm4(bAh + swz16(ar,      ahalf)*2, ah0);
    ldsm4(bAh + swz16(ar + 16, ahalf)*2, ah1);
    ldsm4(bAl + swz16(ar,      ahalf)*2, al0);
    ldsm4(bAl + swz16(ar + 16, ahalf)*2, al1);

    uint32_t bhf[8][2], blf[8][2];
#pragma unroll
    for (int pr = 0; pr < 4; pr++) {
      int rr = wn*64 + pr*16 + brl;
      uint32_t r4[4];
      ldsm4(bBh + swz16(rr, bhalf)*2, r4);
      bhf[2*pr][0]=r4[0]; bhf[2*pr][1]=r4[1]; bhf[2*pr+1][0]=r4[2]; bhf[2*pr+1][1]=r4[3];
      ldsm4(bBl + swz16(rr, bhalf)*2, r4);
      blf[2*pr][0]=r4[0]; blf[2*pr][1]=r4[1]; blf[2*pr+1][0]=r4[2]; blf[2*pr+1][1]=r4[3];
    }
#pragma unroll
    for (int n = 0; n < 8; n++) {
      mma_bf16(acc[0][n], ah0, bhf[n]);
      mma_bf16(acc[1][n], ah1, bhf[n]);
      mma_bf16(acc[0][n], ah0, blf[n]);
      mma_bf16(acc[1][n], ah1, blf[n]);
      mma_bf16(acc[0][n], al0, bhf[n]);
      mma_bf16(acc[1][n], al1, bhf[n]);
    }
    if (kt < 63) {
      int nxt = cur ^ 1;
      *(uint4*)&sA[nxt][0][soff] = va;  *(uint4*)&sA[nxt][1][soff] = vb;
      *(uint4*)&sB[nxt][0][soff] = vc;  *(uint4*)&sB[nxt][1][soff] = vd;
    }
    __syncthreads();
  }

  const int g = lane >> 2, t2 = (lane & 3)*2;
#pragma unroll
  for (int m = 0; m < 2; m++) {
    int row = m0 + wm*32 + m*16 + g;
#pragma unroll
    for (int n = 0; n < 8; n++) {
      int col = n0 + wn*64 + n*8 + t2;
      *(float2*)&C[(size_t)row*D_ + col]     = make_float2(acc[m][n][0], acc[m][n][1]);
      *(float2*)&C[(size_t)(row+8)*D_ + col] = make_float2(acc[m][n][2], acc[m][n][3]);
    }
  }
}

// ---------------------------------------------------------------------------
// RoPE + augmentation, output bf16 hi/lo, row-major [bh][s][128]
// kk<64: roped; kk>=64: sq * roped^2   (lambda folded into K side)
// ---------------------------------------------------------------------------
__global__ __launch_bounds__(256) void rope_aug_bf16(const float* __restrict__ src,
    bf16* __restrict__ dh, bf16* __restrict__ dl, float sq) {
  int gid = blockIdx.x*256 + threadIdx.x;
  int p = gid & 31;
  int h = (gid >> 5) & 15;
  int srow = gid >> 9;            // b*S+s, 0..4095
  int b = srow >> 11, s = srow & 2047;
  float t1 = src[(size_t)srow*D_ + h*HD + p];
  float t2 = src[(size_t)srow*D_ + h*HD + p + 32];
  float invf = (float)(1.0 / pow(10000.0, (double)p / 32.0));
  float ang = (float)s * invf;
  float sn, cs; sincosf(ang, &sn, &cs);
  float r1 = t1*cs - t2*sn;
  float r2 = t2*cs + t1*sn;
  size_t base = ((size_t)(b*16 + h)*S_ + s) * KAD;
  float vals[4] = { r1, r2, sq*r1*r1, sq*r2*r2 };
  int kks[4] = { p, p+32, 64+p, 96+p };
#pragma unroll
  for (int i = 0; i < 4; i++) {
    bf16 hi = __float2bfloat16_rn(vals[i]);
    dh[base + kks[i]] = hi;
    dl[base + kks[i]] = __float2bfloat16_rn(vals[i] - __bfloat162float(hi));
  }
}

// ---------------------------------------------------------------------------
// Flash attention, causal, augmented d=128, tensor-core 3-pass bf16.
// q-tile 128, kv-tile 64. 8 warps; warp owns 16 q rows x full tile width.
// ---------------------------------------------------------------------------
__global__ __launch_bounds__(256) void flash_bf16(
    const bf16* __restrict__ Qh, const bf16* __restrict__ Ql,
    const bf16* __restrict__ Kh, const bf16* __restrict__ Kl,
    const bf16* __restrict__ Vh, const bf16* __restrict__ Vl,
    float* __restrict__ O) {
  extern __shared__ __align__(16) bf16 sm[];
  const int bh = blockIdx.y;
  const int qi = (int)gridDim.x - 1 - (int)blockIdx.x;  // heavy tiles first
  const int b = bh >> 4, h = bh & 15;
  const int tid = threadIdx.x, w = tid >> 5, lane = tid & 31;
  const uint32_t smb = (uint32_t)__cvta_generic_to_shared(sm);

  // smem element offsets
  const int KH0 = 0, KL0 = 8192, VH0 = 16384, VL0 = 20480;   // K/V phase
  // Q phase uses [0, 16384) hi and [16384, 32768) lo

  // ---- load Q tile (128x128) and build persistent fragments ----
  const uint4* qgh = (const uint4*)(Qh + ((size_t)bh*S_ + (size_t)qi*128) * KAD);
  const uint4* qgl = (const uint4*)(Ql + ((size_t)bh*S_ + (size_t)qi*128) * KAD);
#pragma unroll
  for (int it = 0; it < 8; it++) {
    int idx = it*256 + tid;
    int r = idx >> 4, c = idx & 15;
    uint32_t off = r*128 + ((c ^ (r & 7)) << 3);
    *(uint4*)&sm[off]         = qgh[idx];
    *(uint4*)&sm[16384 + off] = qgl[idx];
  }
  __syncthreads();

  uint32_t qfh[8][4], qfl[8][4];
  {
    int r = w*16 + (lane & 15);
#pragma unroll
    for (int ka = 0; ka < 8; ka++) {
      int c = ka*2 + (lane >> 4);
      uint32_t off = (uint32_t)(r*128 + ((c ^ (r & 7)) << 3));
      ldsm4(smb + off*2, qfh[ka]);
      ldsm4(smb + (16384 + off)*2, qfl[ka]);
    }
  }
  __syncthreads();

  float m0r = -1e30f, m1r = -1e30f, l0 = 0.f, l1 = 0.f;
  float oacc[8][4];
#pragma unroll
  for (int j=0;j<8;j++)
#pragma unroll
    for (int e=0;e<4;e++) oacc[j][e] = 0.f;

  const int nkv = 2*qi + 2;
  const int rg0 = qi*128 + w*16 + (lane >> 2);
  const bf16* vgh = Vh + ((size_t)b*S_)*D_ + h*HD;
  const bf16* vgl = Vl + ((size_t)b*S_)*D_ + h*HD;

  for (int kb = 0; kb < nkv; kb++) {
    // load K tile (64x128) hi+lo
    const uint4* kgh = (const uint4*)(Kh + ((size_t)bh*S_ + (size_t)kb*64) * KAD);
    const uint4* kgl = (const uint4*)(Kl + ((size_t)bh*S_ + (size_t)kb*64) * KAD);
#pragma unroll
    for (int it = 0; it < 4; it++) {
      int idx = it*256 + tid;
      int r = idx >> 4, c = idx & 15;
      uint32_t off = r*128 + ((c ^ (r & 7)) << 3);
      *(uint4*)&sm[KH0 + off] = kgh[idx];
      *(uint4*)&sm[KL0 + off] = kgl[idx];
    }
    // load V tile (64x64) hi+lo
#pragma unroll
    for (int it = 0; it < 2; it++) {
      int idx = it*256 + tid;
      int r = idx >> 3, c = idx & 7;
      uint32_t off = r*64 + ((c ^ (r & 7)) << 3);
      size_t goff = (size_t)(kb*64 + r)*D_ + c*8;
      *(uint4*)&sm[VH0 + off] = *(const uint4*)(vgh + goff);
      *(uint4*)&sm[VL0 + off] = *(const uint4*)(vgl + goff);
    }
    __syncthreads();

    // ---- S = Q . K^T (3-pass) ----
    float sacc[8][4];
#pragma unroll
    for (int j=0;j<8;j++)
#pragma unroll
      for (int e=0;e<4;e++) sacc[j][e] = 0.f;

    const int brl = (lane & 7) + ((lane >> 4) << 3);
    const int bhalf = (lane >> 3) & 1;
#pragma unroll
    for (int ka = 0; ka < 8; ka++) {
      uint32_t bhf[8][2], blf[8][2];
#pragma unroll
      for (int pr = 0; pr < 4; pr++) {
        int rr = pr*16 + brl;
        int c = ka*2 + bhalf;
        uint32_t off = (uint32_t)(rr*128 + ((c ^ (rr & 7)) << 3));
        uint32_t r4[4];
        ldsm4(smb + (KH0 + off)*2, r4);
        bhf[2*pr][0]=r4[0]; bhf[2*pr][1]=r4[1]; bhf[2*pr+1][0]=r4[2]; bhf[2*pr+1][1]=r4[3];
        ldsm4(smb + (KL0 + off)*2, r4);
        blf[2*pr][0]=r4[0]; blf[2*pr][1]=r4[1]; blf[2*pr+1][0]=r4[2]; blf[2*pr+1][1]=r4[3];
      }
#pragma unroll
      for (int j = 0; j < 8; j++) {
        mma_bf16(sacc[j], qfh[ka], bhf[j]);
        mma_bf16(sacc[j], qfh[ka], blf[j]);
        mma_bf16(sacc[j], qfl[ka], bhf[j]);
      }
    }

    // ---- scale + causal mask ----
#pragma unroll
    for (int j = 0; j < 8; j++) {
#pragma unroll
      for (int e = 0; e < 4; e++) {
        float v = sacc[j][e] * 0.125f;
        int row = rg0 + ((e >= 2) ? 8 : 0);
        int col = kb*64 + j*8 + (lane & 3)*2 + (e & 1);
        if (col > row) v = -1e30f;
        sacc[j][e] = v;
      }
    }

    // ---- online softmax (row groups g and g+8; reduce over 4-lane quads) ----
    float mx0 = -1e30f, mx1 = -1e30f;
#pragma unroll
    for (int j = 0; j < 8; j++) {
      mx0 = fmaxf(mx0, fmaxf(sacc[j][0], sacc[j][1]));
      mx1 = fmaxf(mx1, fmaxf(sacc[j][2], sacc[j][3]));
    }
    mx0 = fmaxf(mx0, __shfl_xor_sync(0xffffffffu, mx0, 1));
    mx0 = fmaxf(mx0, __shfl_xor_sync(0xffffffffu, mx0, 2));
    mx1 = fmaxf(mx1, __shfl_xor_sync(0xffffffffu, mx1, 1));
    mx1 = fmaxf(mx1, __shfl_xor_sync(0xffffffffu, mx1, 2));
    float mn0 = fmaxf(m0r, mx0), mn1 = fmaxf(m1r, mx1);
    float f0 = __expf(m0r - mn0), f1 = __expf(m1r - mn1);
    float s0 = 0.f, s1 = 0.f;
#pragma unroll
    for (int j = 0; j < 8; j++) {
      sacc[j][0] = __expf(sacc[j][0] - mn0);
      sacc[j][1] = __expf(sacc[j][1] - mn0);
      sacc[j][2] = __expf(sacc[j][2] - mn1);
      sacc[j][3] = __expf(sacc[j][3] - mn1);
      s0 += sacc[j][0] + sacc[j][1];
      s1 += sacc[j][2] + sacc[j][3];
    }
    s0 += __shfl_xor_sync(0xffffffffu, s0, 1);
    s0 += __shfl_xor_sync(0xffffffffu, s0, 2);
    s1 += __shfl_xor_sync(0xffffffffu, s1, 1);
    s1 += __shfl_xor_sync(0xffffffffu, s1, 2);
    l0 = l0*f0 + s0;  l1 = l1*f1 + s1;
    m0r = mn0; m1r = mn1;
#pragma unroll
    for (int j = 0; j < 8; j++) {
      oacc[j][0] *= f0; oacc[j][1] *= f0;
      oacc[j][2] *= f1; oacc[j][3] *= f1;
    }

    // ---- P fragments (bf16 hi + lo residual), reuse S accumulator layout ----
    uint32_t pfh[4][4], pfl[4][4];
#pragma unroll
    for (int kt = 0; kt < 4; kt++) {
      int j0 = 2*kt, j1 = 2*kt + 1;
      float p[8] = { sacc[j0][0], sacc[j0][1], sacc[j0][2], sacc[j0][3],
                     sacc[j1][0], sacc[j1][1], sacc[j1][2], sacc[j1][3] };
      float pl[8];
#pragma unroll
      for (int e = 0; e < 8; e++) {
        float hh = __bfloat162float(__float2bfloat16_rn(p[e]));
        pl[e] = p[e] - hh;
      }
      pfh[kt][0] = packbf(p[0], p[1]);  pfh[kt][1] = packbf(p[2], p[3]);
      pfh[kt][2] = packbf(p[4], p[5]);  pfh[kt][3] = packbf(p[6], p[7]);
      pfl[kt][0] = packbf(pl[0], pl[1]); pfl[kt][1] = packbf(pl[2], pl[3]);
      pfl[kt][2] = packbf(pl[4], pl[5]); pfl[kt][3] = packbf(pl[6], pl[7]);
    }

    // ---- O += P . V (3-pass) ----
#pragma unroll
    for (int kt = 0; kt < 4; kt++) {
      uint32_t vhf[8][2], vlf[8][2];
      int vr = kt*16 + (lane & 7) + ((lane >> 3) & 1)*8;
#pragma unroll
      for (int pr = 0; pr < 4; pr++) {
        int c = pr*2 + (lane >> 4);
        uint32_t off = (uint32_t)(vr*64 + ((c ^ (vr & 7)) << 3));
        uint32_t r4[4];
        ldsm4t(smb + (VH0 + off)*2, r4);
        vhf[2*pr][0]=r4[0]; vhf[2*pr][1]=r4[1]; vhf[2*pr+1][0]=r4[2]; vhf[2*pr+1][1]=r4[3];
        ldsm4t(smb + (VL0 + off)*2, r4);
        vlf[2*pr][0]=r4[0]; vlf[2*pr][1]=r4[1]; vlf[2*pr+1][0]=r4[2]; vlf[2*pr+1][1]=r4[3];
      }
#pragma unroll
      for (int j = 0; j < 8; j++) {
        mma_bf16(oacc[j], pfh[kt], vhf[j]);
        mma_bf16(oacc[j], pfh[kt], vlf[j]);
        mma_bf16(oacc[j], pfl[kt], vhf[j]);
      }
    }
    __syncthreads();
  }

  // ---- epilogue: normalize & store O [bh][s][64] ----
  float inv0 = 1.f / l0, inv1 = 1.f / l1;
  float* ob = O + (size_t)bh * S_ * HD;
  int row0 = qi*128 + w*16 + (lane >> 2);
#pragma unroll
  for (int j = 0; j < 8; j++) {
    int col = j*8 + (lane & 3)*2;
    *(float2*)&ob[(size_t)row0*HD + col]     = make_float2(oacc[j][0]*inv0, oacc[j][1]*inv0);
    *(float2*)&ob[(size_t)(row0+8)*HD + col] = make_float2(oacc[j][2]*inv1, oacc[j][3]*inv1);
  }
}

// ---------------------------------------------------------------------------
// merge: out2==out1 algebraically -> v = o + 0.05*o^2*gate_w[d]; transpose to
// [b*S+s][D] and split to bf16 hi/lo for the final GEMM.
// ---------------------------------------------------------------------------
__global__ __launch_bounds__(256) void merge_split(const float* __restrict__ O,
    const float* __restrict__ gate, bf16* __restrict__ mh, bf16* __restrict__ ml) {
  int idx = blockIdx.x*256 + threadIdx.x;
  int d = idx & 63;
  int h = (idx >> 6) & 15;
  int row = idx >> 10;
  int b = row >> 11, s = row & 2047;
  float o = O[(((size_t)(b*16 + h)*S_ + s) << 6) + d];
  float g = gate[d];
  float v = o + 0.05f*o*o*g;
  bf16 hi = __float2bfloat16_rn(v);
  mh[idx] = hi;
  ml[idx] = __float2bfloat16_rn(v - __bfloat162float(hi));
}

extern "C" void kernel_launch(void* const* d_in, const int* in_sizes, int n_in,
                              void* d_out, int out_size) {
  const float* x  = (const float*)d_in[0];
  const float* Wq = (const float*)d_in[1];
  const float* Wk = (const float*)d_in[2];
  const float* Wv = (const float*)d_in[3];
  const float* Wo = (const float*)d_in[4];
  const float* gw = (const float*)d_in[5];
  float* out = (float*)d_out;

  float *q,*k,*v,*o;
  bf16 *xh,*xl,*wqh,*wql,*wkh,*wkl,*wvh,*wvl,*woh,*wol;
  bf16 *qah,*qal,*kah,*kal,*vh,*vl,*mh,*ml;
  cudaGetSymbolAddress((void**)&q, g_q);   cudaGetSymbolAddress((void**)&k, g_k);
  cudaGetSymbolAddress((void**)&v, g_v);   cudaGetSymbolAddress((void**)&o, g_o);
  cudaGetSymbolAddress((void**)&xh, g_xh); cudaGetSymbolAddress((void**)&xl, g_xl);
  cudaGetSymbolAddress((void**)&wqh, g_wqh); cudaGetSymbolAddress((void**)&wql, g_wql);
  cudaGetSymbolAddress((void**)&wkh, g_wkh); cudaGetSymbolAddress((void**)&wkl, g_wkl);
  cudaGetSymbolAddress((void**)&wvh, g_wvh); cudaGetSymbolAddress((void**)&wvl, g_wvl);
  cudaGetSymbolAddress((void**)&woh, g_woh); cudaGetSymbolAddress((void**)&wol, g_wol);
  cudaGetSymbolAddress((void**)&qah, g_qah); cudaGetSymbolAddress((void**)&qal, g_qal);
  cudaGetSymbolAddress((void**)&kah, g_kah); cudaGetSymbolAddress((void**)&kal, g_kal);
  cudaGetSymbolAddress((void**)&vh, g_vh);   cudaGetSymbolAddress((void**)&vl, g_vl);
  cudaGetSymbolAddress((void**)&mh, g_mh);   cudaGetSymbolAddress((void**)&ml, g_ml);

  split4<<<4096, 256>>>(x,  xh,  xl,  MROWS*D_/4);
  split4<<<1024, 256>>>(Wq, wqh, wql, D_*D_/4);
  split4<<<1024, 256>>>(Wk, wkh, wkl, D_*D_/4);
  split4<<<1024, 256>>>(Wv, wvh, wvl, D_*D_/4);
  split4<<<1024, 256>>>(Wo, woh, wol, D_*D_/4);

  dim3 gg(32, 8);
  gemm_bf16<<<gg, 256>>>(xh, xl, wqh, wql, q);
  gemm_bf16<<<gg, 256>>>(xh, xl, wkh, wkl, k);
  gemm_bf16<<<gg, 256>>>(xh, xl, wvh, wvl, v);

  rope_aug_bf16<<<8192, 256>>>(q, qah, qal, 1.0f);
  rope_aug_bf16<<<8192, 256>>>(k, kah, kal, 0.1f);
  split4<<<4096, 256>>>(v, vh, vl, MROWS*D_/4);

  cudaFuncSetAttribute(flash_bf16, cudaFuncAttributeMaxDynamicSharedMemorySize, 65536);
  flash_bf16<<<dim3(16, 32), 256, 65536>>>(qah, qal, kah, kal, vh, vl, o);

  merge_split<<<16384, 256>>>(o, gw, mh, ml);

  gemm_bf16<<<gg, 256>>>(mh, ml, woh, wol, out);
}

// round 4
// speedup vs baseline: 3.5298x; 1.1498x over previous
#include <cuda_runtime.h>
#include <cuda_bf16.h>
#include <cstdint>
#include <stdint.h>
#include <math.h>

#define B_ 2
#define S_ 2048
#define D_ 1024
#define H_ 16
#define HD 64
#define BH_ (B_*H_)
#define KAD 128
#define MROWS (B_*S_)

typedef __nv_bfloat16 bf16;

// ---- scratch (static device arrays; no allocation allowed) ----
__device__ float g_q[MROWS * D_];
__device__ float g_k[MROWS * D_];
__device__ bf16 g_xh[MROWS * D_], g_xl[MROWS * D_];
__device__ bf16 g_wqh[D_*D_], g_wql[D_*D_];
__device__ bf16 g_wkh[D_*D_], g_wkl[D_*D_];
__device__ bf16 g_wvh[D_*D_], g_wvl[D_*D_];
__device__ bf16 g_woh[D_*D_], g_wol[D_*D_];
__device__ bf16 g_qah[BH_*S_*KAD], g_qal[BH_*S_*KAD];
__device__ bf16 g_kah[BH_*S_*KAD], g_kal[BH_*S_*KAD];
__device__ bf16 g_vh[MROWS * D_], g_vl[MROWS * D_];
__device__ bf16 g_mh[MROWS * D_], g_ml[MROWS * D_];

// ---- mma / ldmatrix / cp.async helpers ----
__device__ __forceinline__ void ldsm4(uint32_t addr, uint32_t r[4]) {
  asm volatile("ldmatrix.sync.aligned.m8n8.x4.shared.b16 {%0,%1,%2,%3},[%4];"
    : "=r"(r[0]),"=r"(r[1]),"=r"(r[2]),"=r"(r[3]) : "r"(addr));
}
__device__ __forceinline__ void ldsm4t(uint32_t addr, uint32_t r[4]) {
  asm volatile("ldmatrix.sync.aligned.m8n8.x4.trans.shared.b16 {%0,%1,%2,%3},[%4];"
    : "=r"(r[0]),"=r"(r[1]),"=r"(r[2]),"=r"(r[3]) : "r"(addr));
}
__device__ __forceinline__ void mma_bf16(float c[4], const uint32_t a[4], const uint32_t b[2]) {
  asm volatile("mma.sync.aligned.m16n8k16.row.col.f32.bf16.bf16.f32 "
    "{%0,%1,%2,%3},{%4,%5,%6,%7},{%8,%9},{%0,%1,%2,%3};"
    : "+f"(c[0]),"+f"(c[1]),"+f"(c[2]),"+f"(c[3])
    : "r"(a[0]),"r"(a[1]),"r"(a[2]),"r"(a[3]),"r"(b[0]),"r"(b[1]));
}
__device__ __forceinline__ uint32_t packbf(float lo, float hi) {
  uint32_t r;
  asm("cvt.rn.bf16x2.f32 %0, %1, %2;" : "=r"(r) : "f"(hi), "f"(lo));
  return r;
}
__device__ __forceinline__ void cpasync16(uint32_t dst, const void* src) {
  asm volatile("cp.async.cg.shared.global [%0], [%1], 16;" :: "r"(dst), "l"(src));
}
#define CP_COMMIT() asm volatile("cp.async.commit_group;")
#define CP_WAIT0()  asm volatile("cp.async.wait_group 0;")

// swizzle for 32-col bf16 rows (64B): conflict-free for ldmatrix + 16B stores
__device__ __forceinline__ uint32_t swz32(int row, int c) {
  return (uint32_t)(row*32 + ((c ^ ((row>>1)&3)) << 3));
}

// ---------------------------------------------------------------------------
// split: fp32 -> bf16 hi + bf16 lo residual
// ---------------------------------------------------------------------------
__global__ __launch_bounds__(256) void split4(const float* __restrict__ in,
                                              bf16* __restrict__ h, bf16* __restrict__ l, int n4) {
  int i = blockIdx.x*256 + threadIdx.x;
  if (i >= n4) return;
  float4 v = ((const float4*)in)[i];
  bf16 hx = __float2bfloat16_rn(v.x), hy = __float2bfloat16_rn(v.y);
  bf16 hz = __float2bfloat16_rn(v.z), hw = __float2bfloat16_rn(v.w);
  __nv_bfloat162* hp = (__nv_bfloat162*)h;
  __nv_bfloat162* lp = (__nv_bfloat162*)l;
  hp[2*i]   = __nv_bfloat162(hx, hy);
  hp[2*i+1] = __nv_bfloat162(hz, hw);
  lp[2*i]   = __nv_bfloat162(__float2bfloat16_rn(v.x - __bfloat162float(hx)),
                             __float2bfloat16_rn(v.y - __bfloat162float(hy)));
  lp[2*i+1] = __nv_bfloat162(__float2bfloat16_rn(v.z - __bfloat162float(hz)),
                             __float2bfloat16_rn(v.w - __bfloat162float(hw)));
}

// ---------------------------------------------------------------------------
// GEMM (3-pass bf16 split, cp.async 2-stage): C[m,n] = sum_k A[m,k]*W[n,k].
// 128x128 tile, BK=32, 256 threads / 8 warps, warp tile 32x64.
// Output: f32 C (if Cl==nullptr) else bf16 hi/lo split (Ch, Cl).
// Dynamic smem: 64KB. Elem layout: A hi/lo at (st*2+p)*4096, B at 16384+...
// ---------------------------------------------------------------------------
__device__ __forceinline__ void gemm_stage(uint32_t smb, int st,
    const bf16* gAh, const bf16* gAl, const bf16* gBh, const bf16* gBl,
    int kt, int crow, int cc0) {
  const uint32_t aH = smb + (uint32_t)((st*2+0)*4096)*2;
  const uint32_t aL = smb + (uint32_t)((st*2+1)*4096)*2;
  const uint32_t bH = smb + (uint32_t)(16384 + (st*2+0)*4096)*2;
  const uint32_t bL = smb + (uint32_t)(16384 + (st*2+1)*4096)*2;
#pragma unroll
  for (int q2 = 0; q2 < 2; q2++) {
    int c = cc0 + q2;
    uint32_t so = swz32(crow, c)*2;
    int gc = kt*32 + c*8;
    cpasync16(aH + so, gAh + gc);
    cpasync16(aL + so, gAl + gc);
    cpasync16(bH + so, gBh + gc);
    cpasync16(bL + so, gBl + gc);
  }
}

__global__ __launch_bounds__(256) void gemm_bf16(
    const bf16* __restrict__ Ah, const bf16* __restrict__ Al,
    const bf16* __restrict__ Bh, const bf16* __restrict__ Bl,
    float* __restrict__ C, bf16* __restrict__ Ch, bf16* __restrict__ Cl) {
  extern __shared__ __align__(16) bf16 smg[];
  const int tid = threadIdx.x;
  const int w = tid >> 5, lane = tid & 31;
  const int wm = w & 3, wn = w >> 2;
  const int m0 = blockIdx.x * 128, n0 = blockIdx.y * 128;
  const uint32_t smb = (uint32_t)__cvta_generic_to_shared(smg);

  const int crow = tid >> 1;
  const int cc0 = (tid & 1) * 2;
  const bf16* gAh = Ah + (size_t)(m0+crow)*D_;
  const bf16* gAl = Al + (size_t)(m0+crow)*D_;
  const bf16* gBh = Bh + (size_t)(n0+crow)*D_;
  const bf16* gBl = Bl + (size_t)(n0+crow)*D_;

  gemm_stage(smb, 0, gAh, gAl, gBh, gBl, 0, crow, cc0);
  CP_COMMIT();

  float acc[2][8][4];
#pragma unroll
  for (int m=0;m<2;m++)
#pragma unroll
    for (int n=0;n<8;n++)
#pragma unroll
      for (int e=0;e<4;e++) acc[m][n][e] = 0.f;

  const int arow = wm*32 + (lane & 15);
  const int ahalf = lane >> 4;
  const int brl = (lane & 7) + ((lane >> 4) << 3);
  const int bhalf = (lane >> 3) & 1;

  for (int kt = 0; kt < 32; kt++) {
    const int st = kt & 1;
    CP_WAIT0();
    __syncthreads();
    if (kt < 31) { gemm_stage(smb, st^1, gAh, gAl, gBh, gBl, kt+1, crow, cc0); CP_COMMIT(); }

    const uint32_t aH = smb + (uint32_t)((st*2+0)*4096)*2;
    const uint32_t aL = smb + (uint32_t)((st*2+1)*4096)*2;
    const uint32_t bH = smb + (uint32_t)(16384 + (st*2+0)*4096)*2;
    const uint32_t bL = smb + (uint32_t)(16384 + (st*2+1)*4096)*2;
#pragma unroll
    for (int ka = 0; ka < 2; ka++) {
      const int cca = ka*2 + ahalf;
      uint32_t ah0[4], ah1[4], al0[4], al1[4];
      ldsm4(aH + swz32(arow,      cca)*2, ah0);
      ldsm4(aH + swz32(arow + 16, cca)*2, ah1);
      ldsm4(aL + swz32(arow,      cca)*2, al0);
      ldsm4(aL + swz32(arow + 16, cca)*2, al1);

      const int ccb = ka*2 + bhalf;
      uint32_t bhf[8][2], blf[8][2];
#pragma unroll
      for (int pr = 0; pr < 4; pr++) {
        int rr = wn*64 + pr*16 + brl;
        uint32_t r4[4];
        ldsm4(bH + swz32(rr, ccb)*2, r4);
        bhf[2*pr][0]=r4[0]; bhf[2*pr][1]=r4[1]; bhf[2*pr+1][0]=r4[2]; bhf[2*pr+1][1]=r4[3];
        ldsm4(bL + swz32(rr, ccb)*2, r4);
        blf[2*pr][0]=r4[0]; blf[2*pr][1]=r4[1]; blf[2*pr+1][0]=r4[2]; blf[2*pr+1][1]=r4[3];
      }
#pragma unroll
      for (int n = 0; n < 8; n++) {
        mma_bf16(acc[0][n], ah0, bhf[n]);
        mma_bf16(acc[1][n], ah1, bhf[n]);
        mma_bf16(acc[0][n], ah0, blf[n]);
        mma_bf16(acc[1][n], ah1, blf[n]);
        mma_bf16(acc[0][n], al0, bhf[n]);
        mma_bf16(acc[1][n], al1, bhf[n]);
      }
    }
  }

  const int g = lane >> 2, t2 = (lane & 3)*2;
  if (Cl == nullptr) {
#pragma unroll
    for (int m = 0; m < 2; m++) {
      int row = m0 + wm*32 + m*16 + g;
#pragma unroll
      for (int n = 0; n < 8; n++) {
        int col = n0 + wn*64 + n*8 + t2;
        *(float2*)&C[(size_t)row*D_ + col]     = make_float2(acc[m][n][0], acc[m][n][1]);
        *(float2*)&C[(size_t)(row+8)*D_ + col] = make_float2(acc[m][n][2], acc[m][n][3]);
      }
    }
  } else {
#pragma unroll
    for (int m = 0; m < 2; m++) {
      int row = m0 + wm*32 + m*16 + g;
#pragma unroll
      for (int n = 0; n < 8; n++) {
        int col = n0 + wn*64 + n*8 + t2;
#pragma unroll
        for (int half = 0; half < 2; half++) {
          float v0 = acc[m][n][half*2], v1 = acc[m][n][half*2+1];
          bf16 h0 = __float2bfloat16_rn(v0), h1 = __float2bfloat16_rn(v1);
          size_t off = (size_t)(row + half*8)*D_ + col;
          *(__nv_bfloat162*)&Ch[off] = __nv_bfloat162(h0, h1);
          *(__nv_bfloat162*)&Cl[off] = __nv_bfloat162(
              __float2bfloat16_rn(v0 - __bfloat162float(h0)),
              __float2bfloat16_rn(v1 - __bfloat162float(h1)));
        }
      }
    }
  }
}

// ---------------------------------------------------------------------------
// RoPE + augmentation, output bf16 hi/lo, row-major [bh][s][128]
// ---------------------------------------------------------------------------
__global__ __launch_bounds__(256) void rope_aug_bf16(const float* __restrict__ src,
    bf16* __restrict__ dh, bf16* __restrict__ dl, float sq) {
  int gid = blockIdx.x*256 + threadIdx.x;
  int p = gid & 31;
  int h = (gid >> 5) & 15;
  int srow = gid >> 9;
  int b = srow >> 11, s = srow & 2047;
  float t1 = src[(size_t)srow*D_ + h*HD + p];
  float t2 = src[(size_t)srow*D_ + h*HD + p + 32];
  float invf = (float)(1.0 / pow(10000.0, (double)p / 32.0));
  float ang = (float)s * invf;
  float sn, cs; sincosf(ang, &sn, &cs);
  float r1 = t1*cs - t2*sn;
  float r2 = t2*cs + t1*sn;
  size_t base = ((size_t)(b*16 + h)*S_ + s) * KAD;
  float vals[4] = { r1, r2, sq*r1*r1, sq*r2*r2 };
  int kks[4] = { p, p+32, 64+p, 96+p };
#pragma unroll
  for (int i = 0; i < 4; i++) {
    bf16 hi = __float2bfloat16_rn(vals[i]);
    dh[base + kks[i]] = hi;
    dl[base + kks[i]] = __float2bfloat16_rn(vals[i] - __bfloat162float(hi));
  }
}

// ---------------------------------------------------------------------------
// Flash attention, causal, augmented d=128, 3-pass bf16, cp.async 2-stage K/V,
// fused gate-merge epilogue writing bf16 hi/lo in [b*S+s][D] layout.
// q-tile 128, kv-tile 64. Dynamic smem 96KB: stage st at st*24576 elems:
//   KH +0 (8192), KL +8192, VH +16384 (4096), VL +20480.
// ---------------------------------------------------------------------------
__device__ __forceinline__ void flash_stage(uint32_t smb, int st, int tid,
    const bf16* kgh_b, const bf16* kgl_b, const bf16* vgh, const bf16* vgl, int kb) {
  const uint32_t KH = smb + (uint32_t)(st*24576)*2;
  const uint32_t KL = KH + 8192*2;
  const uint32_t VH = KH + 16384*2;
  const uint32_t VL = KH + 20480*2;
  const bf16* kgh = kgh_b + (size_t)kb*64*KAD;
  const bf16* kgl = kgl_b + (size_t)kb*64*KAD;
#pragma unroll
  for (int it = 0; it < 4; it++) {
    int idx = it*256 + tid;
    int r = idx >> 4, c = idx & 15;
    uint32_t off = (uint32_t)(r*128 + ((c ^ (r & 7)) << 3))*2;
    cpasync16(KH + off, kgh + idx*8);
    cpasync16(KL + off, kgl + idx*8);
  }
#pragma unroll
  for (int it = 0; it < 2; it++) {
    int idx = it*256 + tid;
    int r = idx >> 3, c = idx & 7;
    uint32_t off = (uint32_t)(r*64 + ((c ^ (r & 7)) << 3))*2;
    size_t goff = (size_t)(kb*64 + r)*D_ + c*8;
    cpasync16(VH + off, vgh + goff);
    cpasync16(VL + off, vgl + goff);
  }
}

__global__ __launch_bounds__(256) void flash_bf16(
    const bf16* __restrict__ Qh, const bf16* __restrict__ Ql,
    const bf16* __restrict__ Kh, const bf16* __restrict__ Kl,
    const bf16* __restrict__ Vh, const bf16* __restrict__ Vl,
    const float* __restrict__ gate,
    bf16* __restrict__ Mh, bf16* __restrict__ Ml) {
  extern __shared__ __align__(16) bf16 sm[];
  const int bh = blockIdx.y;
  const int qi = (int)gridDim.x - 1 - (int)blockIdx.x;  // heavy tiles first
  const int b = bh >> 4, h = bh & 15;
  const int tid = threadIdx.x, w = tid >> 5, lane = tid & 31;
  const uint32_t smb = (uint32_t)__cvta_generic_to_shared(sm);

  // ---- load Q tile (128x128 hi+lo) into smem, build persistent fragments ----
  const uint4* qgh = (const uint4*)(Qh + ((size_t)bh*S_ + (size_t)qi*128) * KAD);
  const uint4* qgl = (const uint4*)(Ql + ((size_t)bh*S_ + (size_t)qi*128) * KAD);
#pragma unroll
  for (int it = 0; it < 8; it++) {
    int idx = it*256 + tid;
    int r = idx >> 4, c = idx & 15;
    uint32_t off = r*128 + ((c ^ (r & 7)) << 3);
    *(uint4*)&sm[off]         = qgh[idx];
    *(uint4*)&sm[16384 + off] = qgl[idx];
  }
  __syncthreads();

  uint32_t qfh[8][4], qfl[8][4];
  {
    int r = w*16 + (lane & 15);
#pragma unroll
    for (int ka = 0; ka < 8; ka++) {
      int c = ka*2 + (lane >> 4);
      uint32_t off = (uint32_t)(r*128 + ((c ^ (r & 7)) << 3));
      ldsm4(smb + off*2, qfh[ka]);
      ldsm4(smb + (16384 + off)*2, qfl[ka]);
    }
  }
  __syncthreads();

  float m0r = -1e30f, m1r = -1e30f, l0 = 0.f, l1 = 0.f;
  float oacc[8][4];
#pragma unroll
  for (int j=0;j<8;j++)
#pragma unroll
    for (int e=0;e<4;e++) oacc[j][e] = 0.f;

  const int nkv = 2*qi + 2;
  const int rg0 = qi*128 + w*16 + (lane >> 2);
  const bf16* kgh_b = Kh + (size_t)bh*S_*KAD;
  const bf16* kgl_b = Kl + (size_t)bh*S_*KAD;
  const bf16* vgh = Vh + ((size_t)b*S_)*D_ + h*HD;
  const bf16* vgl = Vl + ((size_t)b*S_)*D_ + h*HD;

  flash_stage(smb, 0, tid, kgh_b, kgl_b, vgh, vgl, 0);
  CP_COMMIT();

  const int brl = (lane & 7) + ((lane >> 4) << 3);
  const int bhalf = (lane >> 3) & 1;

  for (int kb = 0; kb < nkv; kb++) {
    const int st = kb & 1;
    CP_WAIT0();
    __syncthreads();
    if (kb + 1 < nkv) { flash_stage(smb, st^1, tid, kgh_b, kgl_b, vgh, vgl, kb+1); CP_COMMIT(); }

    const uint32_t KH = smb + (uint32_t)(st*24576)*2;
    const uint32_t KL = KH + 8192*2;
    const uint32_t VH = KH + 16384*2;
    const uint32_t VL = KH + 20480*2;

    // ---- S = Q . K^T (3-pass) ----
    float sacc[8][4];
#pragma unroll
    for (int j=0;j<8;j++)
#pragma unroll
      for (int e=0;e<4;e++) sacc[j][e] = 0.f;

#pragma unroll
    for (int ka = 0; ka < 8; ka++) {
      uint32_t bhf[8][2], blf[8][2];
#pragma unroll
      for (int pr = 0; pr < 4; pr++) {
        int rr = pr*16 + brl;
        int c = ka*2 + bhalf;
        uint32_t off = (uint32_t)(rr*128 + ((c ^ (rr & 7)) << 3))*2;
        uint32_t r4[4];
        ldsm4(KH + off, r4);
        bhf[2*pr][0]=r4[0]; bhf[2*pr][1]=r4[1]; bhf[2*pr+1][0]=r4[2]; bhf[2*pr+1][1]=r4[3];
        ldsm4(KL + off, r4);
        blf[2*pr][0]=r4[0]; blf[2*pr][1]=r4[1]; blf[2*pr+1][0]=r4[2]; blf[2*pr+1][1]=r4[3];
      }
#pragma unroll
      for (int j = 0; j < 8; j++) {
        mma_bf16(sacc[j], qfh[ka], bhf[j]);
        mma_bf16(sacc[j], qfh[ka], blf[j]);
        mma_bf16(sacc[j], qfl[ka], bhf[j]);
      }
    }

    // ---- scale + causal mask ----
#pragma unroll
    for (int j = 0; j < 8; j++) {
#pragma unroll
      for (int e = 0; e < 4; e++) {
        float v = sacc[j][e] * 0.125f;
        int row = rg0 + ((e >= 2) ? 8 : 0);
        int col = kb*64 + j*8 + (lane & 3)*2 + (e & 1);
        if (col > row) v = -1e30f;
        sacc[j][e] = v;
      }
    }

    // ---- online softmax ----
    float mx0 = -1e30f, mx1 = -1e30f;
#pragma unroll
    for (int j = 0; j < 8; j++) {
      mx0 = fmaxf(mx0, fmaxf(sacc[j][0], sacc[j][1]));
      mx1 = fmaxf(mx1, fmaxf(sacc[j][2], sacc[j][3]));
    }
    mx0 = fmaxf(mx0, __shfl_xor_sync(0xffffffffu, mx0, 1));
    mx0 = fmaxf(mx0, __shfl_xor_sync(0xffffffffu, mx0, 2));
    mx1 = fmaxf(mx1, __shfl_xor_sync(0xffffffffu, mx1, 1));
    mx1 = fmaxf(mx1, __shfl_xor_sync(0xffffffffu, mx1, 2));
    float mn0 = fmaxf(m0r, mx0), mn1 = fmaxf(m1r, mx1);
    float f0 = __expf(m0r - mn0), f1 = __expf(m1r - mn1);
    float s0 = 0.f, s1 = 0.f;
#pragma unroll
    for (int j = 0; j < 8; j++) {
      sacc[j][0] = __expf(sacc[j][0] - mn0);
      sacc[j][1] = __expf(sacc[j][1] - mn0);
      sacc[j][2] = __expf(sacc[j][2] - mn1);
      sacc[j][3] = __expf(sacc[j][3] - mn1);
      s0 += sacc[j][0] + sacc[j][1];
      s1 += sacc[j][2] + sacc[j][3];
    }
    s0 += __shfl_xor_sync(0xffffffffu, s0, 1);
    s0 += __shfl_xor_sync(0xffffffffu, s0, 2);
    s1 += __shfl_xor_sync(0xffffffffu, s1, 1);
    s1 += __shfl_xor_sync(0xffffffffu, s1, 2);
    l0 = l0*f0 + s0;  l1 = l1*f1 + s1;
    m0r = mn0; m1r = mn1;
#pragma unroll
    for (int j = 0; j < 8; j++) {
      oacc[j][0] *= f0; oacc[j][1] *= f0;
      oacc[j][2] *= f1; oacc[j][3] *= f1;
    }

    // ---- P fragments (bf16 hi + lo residual) ----
    uint32_t pfh[4][4], pfl[4][4];
#pragma unroll
    for (int kt = 0; kt < 4; kt++) {
      int j0 = 2*kt, j1 = 2*kt + 1;
      float p[8] = { sacc[j0][0], sacc[j0][1], sacc[j0][2], sacc[j0][3],
                     sacc[j1][0], sacc[j1][1], sacc[j1][2], sacc[j1][3] };
      float pl[8];
#pragma unroll
      for (int e = 0; e < 8; e++) {
        float hh = __bfloat162float(__float2bfloat16_rn(p[e]));
        pl[e] = p[e] - hh;
      }
      pfh[kt][0] = packbf(p[0], p[1]);  pfh[kt][1] = packbf(p[2], p[3]);
      pfh[kt][2] = packbf(p[4], p[5]);  pfh[kt][3] = packbf(p[6], p[7]);
      pfl[kt][0] = packbf(pl[0], pl[1]); pfl[kt][1] = packbf(pl[2], pl[3]);
      pfl[kt][2] = packbf(pl[4], pl[5]); pfl[kt][3] = packbf(pl[6], pl[7]);
    }

    // ---- O += P . V (3-pass) ----
#pragma unroll
    for (int kt = 0; kt < 4; kt++) {
      uint32_t vhf[8][2], vlf[8][2];
      int vr = kt*16 + (lane & 7) + ((lane >> 3) & 1)*8;
#pragma unroll
      for (int pr = 0; pr < 4; pr++) {
        int c = pr*2 + (lane >> 4);
        uint32_t off = (uint32_t)(vr*64 + ((c ^ (vr & 7)) << 3))*2;
        uint32_t r4[4];
        ldsm4t(VH + off, r4);
        vhf[2*pr][0]=r4[0]; vhf[2*pr][1]=r4[1]; vhf[2*pr+1][0]=r4[2]; vhf[2*pr+1][1]=r4[3];
        ldsm4t(VL + off, r4);
        vlf[2*pr][0]=r4[0]; vlf[2*pr][1]=r4[1]; vlf[2*pr+1][0]=r4[2]; vlf[2*pr+1][1]=r4[3];
      }
#pragma unroll
      for (int j = 0; j < 8; j++) {
        mma_bf16(oacc[j], pfh[kt], vhf[j]);
        mma_bf16(oacc[j], pfh[kt], vlf[j]);
        mma_bf16(oacc[j], pfl[kt], vhf[j]);
      }
    }
  }

  // ---- epilogue: normalize, gate-merge (out2==out1), write bf16 hi/lo ----
  float inv0 = 1.f / l0, inv1 = 1.f / l1;
  int r0 = qi*128 + w*16 + (lane >> 2);
  int srow0 = b*S_ + r0;
#pragma unroll
  for (int j = 0; j < 8; j++) {
    int d = j*8 + (lane & 3)*2;
    float g0 = gate[d], g1 = gate[d+1];
#pragma unroll
    for (int half = 0; half < 2; half++) {
      float inv = half ? inv1 : inv0;
      float o0 = oacc[j][half*2]   * inv;
      float o1 = oacc[j][half*2+1] * inv;
      float v0 = o0 + 0.05f*o0*o0*g0;
      float v1 = o1 + 0.05f*o1*o1*g1;
      bf16 h0 = __float2bfloat16_rn(v0), h1 = __float2bfloat16_rn(v1);
      size_t off = (size_t)(srow0 + half*8)*D_ + h*HD + d;
      *(__nv_bfloat162*)&Mh[off] = __nv_bfloat162(h0, h1);
      *(__nv_bfloat162*)&Ml[off] = __nv_bfloat162(
          __float2bfloat16_rn(v0 - __bfloat162float(h0)),
          __float2bfloat16_rn(v1 - __bfloat162float(h1)));
    }
  }
}

extern "C" void kernel_launch(void* const* d_in, const int* in_sizes, int n_in,
                              void* d_out, int out_size) {
  const float* x  = (const float*)d_in[0];
  const float* Wq = (const float*)d_in[1];
  const float* Wk = (const float*)d_in[2];
  const float* Wv = (const float*)d_in[3];
  const float* Wo = (const float*)d_in[4];
  const float* gw = (const float*)d_in[5];
  float* out = (float*)d_out;

  float *q,*k;
  bf16 *xh,*xl,*wqh,*wql,*wkh,*wkl,*wvh,*wvl,*woh,*wol;
  bf16 *qah,*qal,*kah,*kal,*vh,*vl,*mh,*ml;
  cudaGetSymbolAddress((void**)&q, g_q);   cudaGetSymbolAddress((void**)&k, g_k);
  cudaGetSymbolAddress((void**)&xh, g_xh); cudaGetSymbolAddress((void**)&xl, g_xl);
  cudaGetSymbolAddress((void**)&wqh, g_wqh); cudaGetSymbolAddress((void**)&wql, g_wql);
  cudaGetSymbolAddress((void**)&wkh, g_wkh); cudaGetSymbolAddress((void**)&wkl, g_wkl);
  cudaGetSymbolAddress((void**)&wvh, g_wvh); cudaGetSymbolAddress((void**)&wvl, g_wvl);
  cudaGetSymbolAddress((void**)&woh, g_woh); cudaGetSymbolAddress((void**)&wol, g_wol);
  cudaGetSymbolAddress((void**)&qah, g_qah); cudaGetSymbolAddress((void**)&qal, g_qal);
  cudaGetSymbolAddress((void**)&kah, g_kah); cudaGetSymbolAddress((void**)&kal, g_kal);
  cudaGetSymbolAddress((void**)&vh, g_vh);   cudaGetSymbolAddress((void**)&vl, g_vl);
  cudaGetSymbolAddress((void**)&mh, g_mh);   cudaGetSymbolAddress((void**)&ml, g_ml);

  cudaFuncSetAttribute(gemm_bf16, cudaFuncAttributeMaxDynamicSharedMemorySize, 65536);
  cudaFuncSetAttribute(flash_bf16, cudaFuncAttributeMaxDynamicSharedMemorySize, 98304);

  split4<<<4096, 256>>>(x,  xh,  xl,  MROWS*D_/4);
  split4<<<1024, 256>>>(Wq, wqh, wql, D_*D_/4);
  split4<<<1024, 256>>>(Wk, wkh, wkl, D_*D_/4);
  split4<<<1024, 256>>>(Wv, wvh, wvl, D_*D_/4);
  split4<<<1024, 256>>>(Wo, woh, wol, D_*D_/4);

  dim3 gg(32, 8);
  gemm_bf16<<<gg, 256, 65536>>>(xh, xl, wqh, wql, q, nullptr, nullptr);
  gemm_bf16<<<gg, 256, 65536>>>(xh, xl, wkh, wkl, k, nullptr, nullptr);
  gemm_bf16<<<gg, 256, 65536>>>(xh, xl, wvh, wvl, nullptr, vh, vl);

  rope_aug_bf16<<<8192, 256>>>(q, qah, qal, 1.0f);
  rope_aug_bf16<<<8192, 256>>>(k, kah, kal, 0.1f);

  flash_bf16<<<dim3(16, 32), 256, 98304>>>(qah, qal, kah, kal, vh, vl, gw, mh, ml);

  gemm_bf16<<<gg, 256, 65536>>>(mh, ml, woh, wol, out, nullptr, nullptr);
}